// round 6
// baseline (speedup 1.0000x reference)
#include <cuda_runtime.h>
#include <cuda_bf16.h>
#include <cstdint>
#include <math.h>

// ---------------- problem constants ----------------
#define BB 2
#define NN 2048
#define DD 2048
#define HH 16
#define QLORA 1536
#define KVLORA 512
#define DNOPE 128
#define DROPE 64
#define DVAL 128
#define QKD 192
#define MROWS (BB*NN)
#define EPS 1e-6f
#define ATTN_SCALE 0.072168783648703220563f

// ---------------- scratch ----------------
__device__ float g_qa  [(size_t)MROWS*QLORA];
__device__ float g_q   [(size_t)MROWS*HH*QKD];
__device__ float g_qT  [(size_t)BB*HH*NN*QKD];
__device__ float g_kva [(size_t)MROWS*(DROPE+KVLORA)];
__device__ float g_kvcn[(size_t)MROWS*KVLORA];
__device__ float g_krope[(size_t)MROWS*DROPE];
__device__ float g_kv  [(size_t)MROWS*HH*(DNOPE+DVAL)];
__device__ float g_kT  [(size_t)BB*HH*NN*QKD];
__device__ float g_vT  [(size_t)BB*HH*NN*DVAL];
__device__ float g_ao  [(size_t)MROWS*HH*DVAL];

// ---------------- helpers ----------------
__device__ __forceinline__ uint32_t f2tf32(float x) {
    uint32_t r;
    asm("cvt.rna.tf32.f32 %0, %1;" : "=r"(r) : "f"(x));
    return r;
}
__device__ __forceinline__ void mma_tf32(float* c, const uint32_t* a, const uint32_t* b) {
    asm volatile(
        "mma.sync.aligned.m16n8k8.row.col.f32.tf32.tf32.f32 "
        "{%0,%1,%2,%3}, {%4,%5,%6,%7}, {%8,%9}, {%0,%1,%2,%3};"
        : "+f"(c[0]), "+f"(c[1]), "+f"(c[2]), "+f"(c[3])
        : "r"(a[0]), "r"(a[1]), "r"(a[2]), "r"(a[3]), "r"(b[0]), "r"(b[1]));
}
__device__ __forceinline__ uint32_t smem_u32(const void* p) {
    uint32_t a;
    asm("{ .reg .u64 t; cvta.to.shared.u64 t, %1; cvt.u32.u64 %0, t; }" : "=r"(a) : "l"(p));
    return a;
}
__device__ __forceinline__ void cp_async16(uint32_t dst, const float* src) {
    asm volatile("cp.async.cg.shared.global [%0], [%1], 16;" :: "r"(dst), "l"(src));
}
#define CP_COMMIT() asm volatile("cp.async.commit_group;" ::: "memory")
#define CP_WAIT1()  asm volatile("cp.async.wait_group 1;" ::: "memory")

__device__ __forceinline__ float block_reduce_sum(float v) {
    __shared__ float red[32];
    int lane = threadIdx.x & 31, w = threadIdx.x >> 5;
    #pragma unroll
    for (int o = 16; o; o >>= 1) v += __shfl_xor_sync(0xffffffffu, v, o);
    if (lane == 0) red[w] = v;
    __syncthreads();
    int nw = blockDim.x >> 5;
    float r = (threadIdx.x < nw) ? red[threadIdx.x] : 0.f;
    if (w == 0) {
        #pragma unroll
        for (int o = 16; o; o >>= 1) r += __shfl_xor_sync(0xffffffffu, r, o);
        if (lane == 0) red[0] = r;
    }
    __syncthreads();
    float out = red[0];
    __syncthreads();
    return out;
}

// ========== tf32 GEMM v2: 128x256 CTA tile, 64x64 warp tile ==========
// C[M,N] = A[M,K] @ B[K,N]. BK=16, 3-stage cp.async pipeline.
// A smem [128][20] floats (pitch 80B), B smem [16][264] floats (pitch 1056B).
// Fragment reads conflict-free: A banks 20g+tg (+4,+160 shifts) distinct;
// B banks 8tg+8j+g distinct. Requires M%128==0, N%256==0, K%16==0.
#define G2_APITCH 20
#define G2_BPITCH 264
#define G2_ABYTES (128 * G2_APITCH * 4)          // 10240
#define G2_BBYTES (16 * G2_BPITCH * 4)           // 16896
#define G2_BUF    (G2_ABYTES + G2_BBYTES)        // 27136
#define G2_SMEM   (3 * G2_BUF)                   // 81408

__global__ __launch_bounds__(256) void gemm2_tf32(
    const float* __restrict__ A, const float* __restrict__ B,
    float* __restrict__ C, int M, int N, int K) {
    extern __shared__ char sm2[];
    const uint32_t sb = smem_u32(sm2);

    const int tid = threadIdx.x;
    const int wid = tid >> 5, lane = tid & 31;
    const int g = lane >> 2, tg = lane & 3;
    const int wm = (wid & 1) * 64;
    const int wn = (wid >> 1) * 64;
    const int row0 = blockIdx.y * 128;
    const int col0 = blockIdx.x * 256;

    // A fill: 2 chunks/thread. chunk c: row=c>>2 (0..127), cq=c&3
    const int ac0 = tid * 2;
    // B fill: 4 chunks/thread. chunk c: krow=c>>6 (0..15), nq=c&63
    const int bc0 = tid * 4;

    #define G2_FILL(t_, b_) do { \
        uint32_t Ad_ = sb + (b_) * G2_BUF; \
        uint32_t Bd_ = Ad_ + G2_ABYTES; \
        int k0_ = (t_) * 16; \
        _Pragma("unroll") \
        for (int i_ = 0; i_ < 2; i_++) { \
            int c_ = ac0 + i_; int r_ = c_ >> 2, cq_ = c_ & 3; \
            cp_async16(Ad_ + r_ * 80 + cq_ * 16, \
                       A + (size_t)(row0 + r_) * K + k0_ + cq_ * 4); \
        } \
        _Pragma("unroll") \
        for (int i_ = 0; i_ < 4; i_++) { \
            int c_ = bc0 + i_; int kr_ = c_ >> 6, nq_ = c_ & 63; \
            cp_async16(Bd_ + kr_ * 1056 + nq_ * 16, \
                       B + (size_t)(k0_ + kr_) * N + col0 + nq_ * 4); \
        } \
    } while (0)

    float acc[4][8][4];
    #pragma unroll
    for (int mf = 0; mf < 4; mf++)
        #pragma unroll
        for (int j = 0; j < 8; j++)
            #pragma unroll
            for (int c = 0; c < 4; c++) acc[mf][j][c] = 0.f;

    const int nt = K / 16;

    G2_FILL(0, 0); CP_COMMIT();
    G2_FILL(1, 1); CP_COMMIT();

    for (int t = 0; t < nt; t++) {
        const int b = t % 3;
        CP_WAIT1();
        __syncthreads();

        const uint32_t Abase = sb + b * G2_BUF;
        const uint32_t Bbase = Abase + G2_ABYTES;
        const float* Asf = reinterpret_cast<const float*>(sm2) + (size_t)b * (G2_BUF / 4);
        const float* Bsf = Asf + G2_ABYTES / 4;
        (void)Abase; (void)Bbase;

        #pragma unroll
        for (int s = 0; s < 2; s++) {
            uint32_t af[4][4];
            #pragma unroll
            for (int mf = 0; mf < 4; mf++) {
                int m = wm + mf * 16 + g;
                af[mf][0] = f2tf32(Asf[m * G2_APITCH + s * 8 + tg]);
                af[mf][1] = f2tf32(Asf[(m + 8) * G2_APITCH + s * 8 + tg]);
                af[mf][2] = f2tf32(Asf[m * G2_APITCH + s * 8 + tg + 4]);
                af[mf][3] = f2tf32(Asf[(m + 8) * G2_APITCH + s * 8 + tg + 4]);
            }
            uint32_t bf[8][2];
            #pragma unroll
            for (int j = 0; j < 8; j++) {
                int n = wn + j * 8 + g;
                bf[j][0] = f2tf32(Bsf[(s * 8 + tg) * G2_BPITCH + n]);
                bf[j][1] = f2tf32(Bsf[(s * 8 + tg + 4) * G2_BPITCH + n]);
            }
            #pragma unroll
            for (int mf = 0; mf < 4; mf++)
                #pragma unroll
                for (int j = 0; j < 8; j++)
                    mma_tf32(acc[mf][j], af[mf], bf[j]);
        }

        __syncthreads();  // all warps done with buffer (t-1)%3 == (t+2)%3 before refill
        if (t + 2 < nt) {
            G2_FILL(t + 2, (t + 2) % 3);
        }
        CP_COMMIT();
    }

    // epilogue
    #pragma unroll
    for (int mf = 0; mf < 4; mf++) {
        #pragma unroll
        for (int j = 0; j < 8; j++) {
            int r = row0 + wm + mf * 16 + g;
            int c = col0 + wn + j * 8 + tg * 2;
            *reinterpret_cast<float2*>(C + (size_t)r * N + c) =
                make_float2(acc[mf][j][0], acc[mf][j][1]);
            *reinterpret_cast<float2*>(C + (size_t)(r + 8) * N + c) =
                make_float2(acc[mf][j][2], acc[mf][j][3]);
        }
    }
    #undef G2_FILL
}

// ---------------- legacy tf32 GEMM (for N=576) -------------------------
template <int BN>
__global__ __launch_bounds__(256) void gemm_tf32(
    const float* __restrict__ A, const float* __restrict__ B,
    float* __restrict__ C, int M, int N, int K) {
    constexpr int NFRAG = BN / 16;
    constexpr int BPITCH = BN + 8;
    __shared__ uint32_t As[2][16][136];
    __shared__ uint32_t Bs[2][16][BPITCH];

    const int tid = threadIdx.x;
    const int wid = tid >> 5, lane = tid & 31;
    const int g = lane >> 2, tg = lane & 3;
    const int wm = (wid & 3) * 32;
    const int wn = (wid >> 2) * (BN / 2);
    const int row0 = blockIdx.y * 128;
    const int col0 = blockIdx.x * BN;

    const int ar  = tid >> 2;
    const int akc = (tid & 3) * 4;
    const float* Ag0 = A + (size_t)(row0 + ar) * K + akc;
    const float* Ag1 = Ag0 + (size_t)64 * K;

    int brow, bcol;
    if (BN == 128) { brow = tid >> 5; bcol = (tid & 31) * 4; }
    else           { brow = tid >> 4; bcol = (tid & 15) * 4; }
    const float* Bg0 = B + (size_t)brow * N + col0 + bcol;
    const float* Bg1 = Bg0 + (size_t)8 * N;

    float acc[2][NFRAG][4];
    #pragma unroll
    for (int i = 0; i < 2; i++)
        #pragma unroll
        for (int j = 0; j < NFRAG; j++)
            #pragma unroll
            for (int k = 0; k < 4; k++) acc[i][j][k] = 0.f;

    const int ntiles = K / 16;
    {
        float4 va0 = *reinterpret_cast<const float4*>(Ag0);
        float4 va1 = *reinterpret_cast<const float4*>(Ag1);
        As[0][akc + 0][ar] = f2tf32(va0.x); As[0][akc + 1][ar] = f2tf32(va0.y);
        As[0][akc + 2][ar] = f2tf32(va0.z); As[0][akc + 3][ar] = f2tf32(va0.w);
        As[0][akc + 0][ar + 64] = f2tf32(va1.x); As[0][akc + 1][ar + 64] = f2tf32(va1.y);
        As[0][akc + 2][ar + 64] = f2tf32(va1.z); As[0][akc + 3][ar + 64] = f2tf32(va1.w);
        float4 vb0 = *reinterpret_cast<const float4*>(Bg0);
        uint4 u0 = make_uint4(f2tf32(vb0.x), f2tf32(vb0.y), f2tf32(vb0.z), f2tf32(vb0.w));
        *reinterpret_cast<uint4*>(&Bs[0][brow][bcol]) = u0;
        if (BN == 128) {
            float4 vb1 = *reinterpret_cast<const float4*>(Bg1);
            uint4 u1 = make_uint4(f2tf32(vb1.x), f2tf32(vb1.y), f2tf32(vb1.z), f2tf32(vb1.w));
            *reinterpret_cast<uint4*>(&Bs[0][brow + 8][bcol]) = u1;
        }
    }
    __syncthreads();

    for (int t = 0; t < ntiles; t++) {
        const int cur = t & 1;
        float4 na0, na1, nb0, nb1;
        const bool more = (t + 1 < ntiles);
        if (more) {
            na0 = *reinterpret_cast<const float4*>(Ag0 + (t + 1) * 16);
            na1 = *reinterpret_cast<const float4*>(Ag1 + (t + 1) * 16);
            nb0 = *reinterpret_cast<const float4*>(Bg0 + (size_t)(t + 1) * 16 * N);
            if (BN == 128)
                nb1 = *reinterpret_cast<const float4*>(Bg1 + (size_t)(t + 1) * 16 * N);
        }
        #pragma unroll
        for (int s = 0; s < 2; s++) {
            uint32_t af[2][4];
            #pragma unroll
            for (int mf = 0; mf < 2; mf++) {
                int m = wm + mf * 16 + g;
                af[mf][0] = As[cur][s * 8 + tg    ][m];
                af[mf][1] = As[cur][s * 8 + tg    ][m + 8];
                af[mf][2] = As[cur][s * 8 + tg + 4][m];
                af[mf][3] = As[cur][s * 8 + tg + 4][m + 8];
            }
            uint32_t bf[NFRAG][2];
            #pragma unroll
            for (int j = 0; j < NFRAG; j++) {
                int n = wn + j * 8 + g;
                bf[j][0] = Bs[cur][s * 8 + tg    ][n];
                bf[j][1] = Bs[cur][s * 8 + tg + 4][n];
            }
            #pragma unroll
            for (int mf = 0; mf < 2; mf++)
                #pragma unroll
                for (int j = 0; j < NFRAG; j++)
                    mma_tf32(acc[mf][j], af[mf], bf[j]);
        }
        if (more) {
            const int nxt = cur ^ 1;
            As[nxt][akc + 0][ar] = f2tf32(na0.x); As[nxt][akc + 1][ar] = f2tf32(na0.y);
            As[nxt][akc + 2][ar] = f2tf32(na0.z); As[nxt][akc + 3][ar] = f2tf32(na0.w);
            As[nxt][akc + 0][ar + 64] = f2tf32(na1.x); As[nxt][akc + 1][ar + 64] = f2tf32(na1.y);
            As[nxt][akc + 2][ar + 64] = f2tf32(na1.z); As[nxt][akc + 3][ar + 64] = f2tf32(na1.w);
            uint4 u0 = make_uint4(f2tf32(nb0.x), f2tf32(nb0.y), f2tf32(nb0.z), f2tf32(nb0.w));
            *reinterpret_cast<uint4*>(&Bs[nxt][brow][bcol]) = u0;
            if (BN == 128) {
                uint4 u1 = make_uint4(f2tf32(nb1.x), f2tf32(nb1.y), f2tf32(nb1.z), f2tf32(nb1.w));
                *reinterpret_cast<uint4*>(&Bs[nxt][brow + 8][bcol]) = u1;
            }
            __syncthreads();
        }
    }
    #pragma unroll
    for (int mf = 0; mf < 2; mf++) {
        #pragma unroll
        for (int j = 0; j < NFRAG; j++) {
            int r = row0 + wm + mf * 16 + g;
            int c = col0 + wn + j * 8 + tg * 2;
            *reinterpret_cast<float2*>(C + (size_t)r * N + c) =
                make_float2(acc[mf][j][0], acc[mf][j][1]);
            *reinterpret_cast<float2*>(C + (size_t)(r + 8) * N + c) =
                make_float2(acc[mf][j][2], acc[mf][j][3]);
        }
    }
}

// ---------------- rmsnorm ----------------
__global__ __launch_bounds__(256) void rmsnorm_kernel(
    const float* __restrict__ in, const float* __restrict__ w,
    float* __restrict__ out, int W) {
    size_t row = blockIdx.x;
    const float* r = in + row * W;
    float ss = 0.f;
    for (int i = threadIdx.x; i < W; i += 256) { float v = r[i]; ss += v * v; }
    ss = block_reduce_sum(ss);
    float sc = rsqrtf(ss / (float)W + EPS);
    for (int i = threadIdx.x; i < W; i += 256)
        out[row * W + i] = r[i] * sc * w[i];
}

// ---------------- q rope + transpose ----------------
__global__ __launch_bounds__(192) void qrope_kernel(
    const float* __restrict__ q, const float* __restrict__ cosv,
    const float* __restrict__ sinv, float* __restrict__ qT) {
    int n = blockIdx.x, h = blockIdx.y, b = blockIdx.z;
    int d = threadIdx.x;
    const float* src = q + ((size_t)(b * NN + n) * HH + h) * QKD;
    float v;
    if (d < DNOPE) {
        v = src[d];
    } else {
        int r = d - DNOPE;
        int i = r >> 1;
        float x0 = src[DNOPE + 2 * i], x1 = src[DNOPE + 2 * i + 1];
        float c = cosv[n * (DROPE / 2) + i], s = sinv[n * (DROPE / 2) + i];
        v = (r & 1) ? fmaf(x0, s, x1 * c) : fmaf(x0, c, -x1 * s);
    }
    qT[(((size_t)b * HH + h) * NN + n) * QKD + d] = v;
}

// ---------------- kv_a ----------------
__global__ __launch_bounds__(256) void kva_kernel(
    const float* __restrict__ kva, const float* __restrict__ kvw,
    const float* __restrict__ cosv, const float* __restrict__ sinv,
    float* __restrict__ krope, float* __restrict__ kvcn) {
    size_t row = blockIdx.x;
    int n = (int)(row % NN);
    const float* src = kva + row * (DROPE + KVLORA);
    float ss = 0.f;
    for (int i = threadIdx.x; i < KVLORA; i += 256) {
        float v = src[DROPE + i]; ss += v * v;
    }
    ss = block_reduce_sum(ss);
    float sc = rsqrtf(ss / (float)KVLORA + EPS);
    for (int i = threadIdx.x; i < KVLORA; i += 256)
        kvcn[row * KVLORA + i] = src[DROPE + i] * sc * kvw[i];
    if (threadIdx.x < DROPE) {
        int t = threadIdx.x;
        int i = t >> 1;
        float x0 = src[2 * i], x1 = src[2 * i + 1];
        float c = cosv[n * (DROPE / 2) + i], s = sinv[n * (DROPE / 2) + i];
        krope[row * DROPE + t] = (t & 1) ? fmaf(x0, s, x1 * c) : fmaf(x0, c, -x1 * s);
    }
}

// ---------------- build K / V ----------------
__global__ __launch_bounds__(192) void buildkv_kernel(
    const float* __restrict__ kv, const float* __restrict__ krope,
    float* __restrict__ kT, float* __restrict__ vT) {
    int n = blockIdx.x, h = blockIdx.y, b = blockIdx.z;
    int d = threadIdx.x;
    size_t row = (size_t)b * NN + n;
    const float* src = kv + (row * HH + h) * (DNOPE + DVAL);
    size_t o = ((size_t)b * HH + h) * NN + n;
    if (d < DNOPE) {
        kT[o * QKD + d] = src[d];
        vT[o * DVAL + d] = src[DNOPE + d];
    } else {
        kT[o * QKD + d] = krope[row * DROPE + (d - DNOPE)];
    }
}

// ---------------- flash attention (tf32 MMA, BQ=128, BK=64) ----------------
#define AQP 196
#define AKP 196
#define AVP 136
#define APP 68
#define SMEM_ATTN ((128*AQP + 64*AKP + 64*AVP + 128*APP) * 4)

__global__ __launch_bounds__(256, 1) void attn_tf32(
    const float* __restrict__ qT, const float* __restrict__ kT,
    const float* __restrict__ vT, float* __restrict__ ao) {
    extern __shared__ uint32_t smu[];
    uint32_t* Qs = smu;
    uint32_t* Ks = Qs + 128 * AQP;
    uint32_t* Vs = Ks + 64 * AKP;
    uint32_t* Ps = Vs + 64 * AVP;

    const int tid = threadIdx.x;
    const int wid = tid >> 5, lane = tid & 31;
    const int g = lane >> 2, tg = lane & 3;
    const int wm = wid * 16;
    const int qt = blockIdx.x, h = blockIdx.y, b = blockIdx.z;
    const int q0 = qt * 128;
    const size_t bh = ((size_t)b * HH + h) * NN;

    const float* Qg = qT + (bh + q0) * QKD;
    for (int i = tid; i < 128 * 48; i += 256) {
        int r = i / 48, c4 = (i % 48) * 4;
        float4 v = *reinterpret_cast<const float4*>(Qg + (size_t)r * QKD + c4);
        uint4 u = make_uint4(f2tf32(v.x), f2tf32(v.y), f2tf32(v.z), f2tf32(v.w));
        *reinterpret_cast<uint4*>(&Qs[r * AQP + c4]) = u;
    }

    float oacc[16][4];
    #pragma unroll
    for (int j = 0; j < 16; j++)
        #pragma unroll
        for (int c = 0; c < 4; c++) oacc[j][c] = 0.f;
    float m0 = -1e30f, m1 = -1e30f, l0 = 0.f, l1 = 0.f;

    const int row0 = q0 + wm + g;
    const int row1 = row0 + 8;
    const int nkt = q0 / 64 + 2;

    for (int kt = 0; kt < nkt; kt++) {
        __syncthreads();
        const float* Kg = kT + (bh + (size_t)kt * 64) * QKD;
        const float* Vg = vT + (bh + (size_t)kt * 64) * DVAL;
        for (int i = tid; i < 64 * 48; i += 256) {
            int r = i / 48, c4 = (i % 48) * 4;
            float4 v = *reinterpret_cast<const float4*>(Kg + (size_t)r * QKD + c4);
            uint4 u = make_uint4(f2tf32(v.x), f2tf32(v.y), f2tf32(v.z), f2tf32(v.w));
            *reinterpret_cast<uint4*>(&Ks[r * AKP + c4]) = u;
        }
        for (int i = tid; i < 64 * 32; i += 256) {
            int r = i / 32, c4 = (i % 32) * 4;
            float4 v = *reinterpret_cast<const float4*>(Vg + (size_t)r * DVAL + c4);
            uint4 u = make_uint4(f2tf32(v.x), f2tf32(v.y), f2tf32(v.z), f2tf32(v.w));
            *reinterpret_cast<uint4*>(&Vs[r * AVP + c4]) = u;
        }
        __syncthreads();

        float sacc[8][4];
        #pragma unroll
        for (int j = 0; j < 8; j++)
            #pragma unroll
            for (int c = 0; c < 4; c++) sacc[j][c] = 0.f;

        #pragma unroll 4
        for (int s = 0; s < 24; s++) {
            uint32_t af[4];
            af[0] = Qs[(wm + g) * AQP + s * 8 + tg];
            af[1] = Qs[(wm + g + 8) * AQP + s * 8 + tg];
            af[2] = Qs[(wm + g) * AQP + s * 8 + tg + 4];
            af[3] = Qs[(wm + g + 8) * AQP + s * 8 + tg + 4];
            #pragma unroll
            for (int j = 0; j < 8; j++) {
                uint32_t bf[2];
                bf[0] = Ks[(j * 8 + g) * AKP + s * 8 + tg];
                bf[1] = Ks[(j * 8 + g) * AKP + s * 8 + tg + 4];
                mma_tf32(sacc[j], af, bf);
            }
        }

        const bool masked = (kt >= 2 * qt);
        #pragma unroll
        for (int j = 0; j < 8; j++) {
            #pragma unroll
            for (int c = 0; c < 4; c++) sacc[j][c] *= ATTN_SCALE;
            if (masked) {
                int col = kt * 64 + j * 8 + 2 * tg;
                if (col     > row0) sacc[j][0] = -1e30f;
                if (col + 1 > row0) sacc[j][1] = -1e30f;
                if (col     > row1) sacc[j][2] = -1e30f;
                if (col + 1 > row1) sacc[j][3] = -1e30f;
            }
        }

        float mx0 = -1e30f, mx1 = -1e30f;
        #pragma unroll
        for (int j = 0; j < 8; j++) {
            mx0 = fmaxf(mx0, fmaxf(sacc[j][0], sacc[j][1]));
            mx1 = fmaxf(mx1, fmaxf(sacc[j][2], sacc[j][3]));
        }
        mx0 = fmaxf(mx0, __shfl_xor_sync(0xffffffffu, mx0, 1));
        mx0 = fmaxf(mx0, __shfl_xor_sync(0xffffffffu, mx0, 2));
        mx1 = fmaxf(mx1, __shfl_xor_sync(0xffffffffu, mx1, 1));
        mx1 = fmaxf(mx1, __shfl_xor_sync(0xffffffffu, mx1, 2));

        float mn0 = fmaxf(m0, mx0), mn1 = fmaxf(m1, mx1);
        float a0 = __expf(m0 - mn0), a1 = __expf(m1 - mn1);
        float ps0 = 0.f, ps1 = 0.f;
        #pragma unroll
        for (int j = 0; j < 8; j++) {
            float p00 = __expf(sacc[j][0] - mn0);
            float p01 = __expf(sacc[j][1] - mn0);
            float p10 = __expf(sacc[j][2] - mn1);
            float p11 = __expf(sacc[j][3] - mn1);
            ps0 += p00 + p01; ps1 += p10 + p11;
            int cc = j * 8 + 2 * tg;
            Ps[(wm + g) * APP + cc]     = f2tf32(p00);
            Ps[(wm + g) * APP + cc + 1] = f2tf32(p01);
            Ps[(wm + g + 8) * APP + cc]     = f2tf32(p10);
            Ps[(wm + g + 8) * APP + cc + 1] = f2tf32(p11);
        }
        ps0 += __shfl_xor_sync(0xffffffffu, ps0, 1);
        ps0 += __shfl_xor_sync(0xffffffffu, ps0, 2);
        ps1 += __shfl_xor_sync(0xffffffffu, ps1, 1);
        ps1 += __shfl_xor_sync(0xffffffffu, ps1, 2);

        l0 = l0 * a0 + ps0; m0 = mn0;
        l1 = l1 * a1 + ps1; m1 = mn1;
        #pragma unroll
        for (int j = 0; j < 16; j++) {
            oacc[j][0] *= a0; oacc[j][1] *= a0;
            oacc[j][2] *= a1; oacc[j][3] *= a1;
        }

        __syncwarp();

        #pragma unroll
        for (int s = 0; s < 8; s++) {
            uint32_t af[4];
            af[0] = Ps[(wm + g) * APP + s * 8 + tg];
            af[1] = Ps[(wm + g + 8) * APP + s * 8 + tg];
            af[2] = Ps[(wm + g) * APP + s * 8 + tg + 4];
            af[3] = Ps[(wm + g + 8) * APP + s * 8 + tg + 4];
            #pragma unroll
            for (int j = 0; j < 16; j++) {
                uint32_t bf[2];
                bf[0] = Vs[(s * 8 + tg) * AVP + j * 8 + g];
                bf[1] = Vs[(s * 8 + tg + 4) * AVP + j * 8 + g];
                mma_tf32(oacc[j], af, bf);
            }
        }
        __syncwarp();
    }

    float inv0 = 1.f / l0, inv1 = 1.f / l1;
    #pragma unroll
    for (int j = 0; j < 16; j++) {
        int col = h * DVAL + j * 8 + 2 * tg;
        *reinterpret_cast<float2*>(ao + ((size_t)b * NN + row0) * (HH * DVAL) + col) =
            make_float2(oacc[j][0] * inv0, oacc[j][1] * inv0);
        *reinterpret_cast<float2*>(ao + ((size_t)b * NN + row1) * (HH * DVAL) + col) =
            make_float2(oacc[j][2] * inv1, oacc[j][3] * inv1);
    }
}

// ---------------- launch -----------------------------------------------------
static void launch_gemm2(const float* A, const float* B, float* C,
                         int M, int N, int K) {
    dim3 grid(N / 256, M / 128);
    gemm2_tf32<<<grid, 256, G2_SMEM>>>(A, B, C, M, N, K);
}

extern "C" void kernel_launch(void* const* d_in, const int* in_sizes, int n_in,
                              void* d_out, int out_size) {
    const float* x        = (const float*)d_in[0];
    const float* rope_cos = (const float*)d_in[2];
    const float* rope_sin = (const float*)d_in[3];
    const float* wq_a     = (const float*)d_in[4];
    const float* q_norm_w = (const float*)d_in[5];
    const float* wq_b     = (const float*)d_in[6];
    const float* wkv_a    = (const float*)d_in[7];
    const float* kv_norm_w= (const float*)d_in[8];
    const float* wkv_b    = (const float*)d_in[9];
    const float* w_out    = (const float*)d_in[10];
    float* out = (float*)d_out;

    float *qa, *q, *qTp, *kva, *kvcn, *krope, *kv, *kTp, *vTp, *aop;
    cudaGetSymbolAddress((void**)&qa,    g_qa);
    cudaGetSymbolAddress((void**)&q,     g_q);
    cudaGetSymbolAddress((void**)&qTp,   g_qT);
    cudaGetSymbolAddress((void**)&kva,   g_kva);
    cudaGetSymbolAddress((void**)&kvcn,  g_kvcn);
    cudaGetSymbolAddress((void**)&krope, g_krope);
    cudaGetSymbolAddress((void**)&kv,    g_kv);
    cudaGetSymbolAddress((void**)&kTp,   g_kT);
    cudaGetSymbolAddress((void**)&vTp,   g_vT);
    cudaGetSymbolAddress((void**)&aop,   g_ao);

    cudaFuncSetAttribute(attn_tf32, cudaFuncAttributeMaxDynamicSharedMemorySize, SMEM_ATTN);
    cudaFuncSetAttribute(gemm2_tf32, cudaFuncAttributeMaxDynamicSharedMemorySize, G2_SMEM);

    // Q path
    launch_gemm2(x, wq_a, qa, MROWS, QLORA, DD);
    rmsnorm_kernel<<<MROWS, 256>>>(qa, q_norm_w, qa, QLORA);
    launch_gemm2(qa, wq_b, q, MROWS, HH * QKD, QLORA);
    {
        dim3 g(NN, HH, BB);
        qrope_kernel<<<g, 192>>>(q, rope_cos, rope_sin, qTp);
    }

    // KV path (wkv_a has N=576 -> legacy path)
    {
        dim3 grid((DROPE + KVLORA) / 64, MROWS / 128);
        gemm_tf32<64><<<grid, 256>>>(x, wkv_a, kva, MROWS, DROPE + KVLORA, DD);
    }
    kva_kernel<<<MROWS, 256>>>(kva, kv_norm_w, rope_cos, rope_sin, krope, kvcn);
    launch_gemm2(kvcn, wkv_b, kv, MROWS, HH * (DNOPE + DVAL), KVLORA);
    {
        dim3 g(NN, HH, BB);
        buildkv_kernel<<<g, 192>>>(kv, krope, kTp, vTp);
    }

    // attention
    {
        dim3 g(NN / 128, HH, BB);
        attn_tf32<<<g, 256, SMEM_ATTN>>>(qTp, kTp, vTp, aop);
    }

    // output projection
    launch_gemm2(aop, w_out, out, MROWS, DD, HH * DVAL);
}